// round 7
// baseline (speedup 1.0000x reference)
#include <cuda_runtime.h>
#include <cuda_bf16.h>
#include <math.h>
#include <stdint.h>

// Problem constants
#define NSEQ 2048
#define DIM  2048
#define HEADS 32
#define KVHEADS 4
#define HD 64
#define KVDIM (KVHEADS*HD)   // 256
#define REP (HEADS/KVHEADS)  // 8

// ---------------- scratch ----------------
__device__ float g_q[NSEQ * DIM];
__device__ float g_k[NSEQ * KVDIM];
__device__ float g_v[NSEQ * KVDIM];
__device__ float g_y[NSEQ * DIM];

// ---------------- helpers ----------------
__device__ __forceinline__ uint32_t f2tf(float x) {
    uint32_t r;
    asm("cvt.rna.tf32.f32 %0, %1;" : "=r"(r) : "f"(x));
    return r;
}

__device__ __forceinline__ float ex2(float x) {
    float r;
    asm("ex2.approx.f32 %0, %1;" : "=f"(r) : "f"(x));
    return r;
}

__device__ __forceinline__ uint32_t pkbf(float x0, float x1) {
    __nv_bfloat162 h = __floats2bfloat162_rn(x0, x1);
    return *reinterpret_cast<uint32_t*>(&h);
}

__device__ __forceinline__ void split2(float x0, float x1, uint32_t& hi, uint32_t& lo) {
    float h0 = __bfloat162float(__float2bfloat16(x0));
    float h1 = __bfloat162float(__float2bfloat16(x1));
    hi = pkbf(h0, h1);
    lo = pkbf(x0 - h0, x1 - h1);
}

__device__ __forceinline__ void mma_tf32(float* d, const uint32_t* a, const uint32_t* b) {
    asm volatile(
        "mma.sync.aligned.m16n8k8.row.col.f32.tf32.tf32.f32 "
        "{%0,%1,%2,%3}, {%4,%5,%6,%7}, {%8,%9}, {%0,%1,%2,%3};"
        : "+f"(d[0]), "+f"(d[1]), "+f"(d[2]), "+f"(d[3])
        : "r"(a[0]), "r"(a[1]), "r"(a[2]), "r"(a[3]), "r"(b[0]), "r"(b[1]));
}

__device__ __forceinline__ void mma_bf16(float* d, const uint32_t* a, const uint32_t* b) {
    asm volatile(
        "mma.sync.aligned.m16n8k16.row.col.f32.bf16.bf16.f32 "
        "{%0,%1,%2,%3}, {%4,%5,%6,%7}, {%8,%9}, {%0,%1,%2,%3};"
        : "+f"(d[0]), "+f"(d[1]), "+f"(d[2]), "+f"(d[3])
        : "r"(a[0]), "r"(a[1]), "r"(a[2]), "r"(a[3]), "r"(b[0]), "r"(b[1]));
}

// Frag-interleaved smem store: pair p (packed hi/lo bf16x2) of given row.
// Row = 32 u32 = 8 chunks of 16B. Logical chunk (ks*4 + qz) holds
// [h(qz), h(qz+4), l(qz), l(qz+4)]; physical chunk ^= (row&1)*4.
__device__ __forceinline__ void store_pair(uint32_t* S, int row, int p,
                                           uint32_t h, uint32_t l) {
    int ks = p >> 3, q = p & 7;
    int chunk = ((ks << 2) + (q & 3)) ^ ((row & 1) << 2);
    int offh = q >> 2;
    int a = row * 32 + chunk * 4;
    S[a + offh]     = h;
    S[a + offh + 2] = l;
}

// ---------------- 3xBF16 NT GEMM ----------------
// C[m][n] = sum_k A[m][k]*B[n][k]. BM=128, BN=64, 256 threads, 8 warps,
// warp-tile 32x32. Frag-interleaved smem -> LDS.128 fragment reads.
__global__ void __launch_bounds__(256, 2)
gemm_bf16(const float* __restrict__ A, const float* __restrict__ Bp,
          float* __restrict__ Cp, const float* __restrict__ B2,
          float* __restrict__ C2, int M, int N, int K)
{
    constexpr int BM = 128, BN = 64, BK = 32;
    constexpr int THREADS = 256;
    constexpr int SA = BM * 32;              // u32
    constexpr int A4T = BM * (BK/4) / THREADS;  // 4
    constexpr int B4T = BN * (BK/4) / THREADS;  // 2

    const float* B = blockIdx.z ? B2 : Bp;
    float*       C = blockIdx.z ? C2 : Cp;

    extern __shared__ uint32_t sm[];
    uint32_t* As = sm;
    uint32_t* Bs = sm + SA;

    const int tid  = threadIdx.x;
    const int lane = tid & 31;
    const int warp = tid >> 5;
    const int wm   = warp >> 1;
    const int wn   = warp & 1;
    const int m0   = blockIdx.y * BM;
    const int n0   = blockIdx.x * BN;
    const int qz   = lane & 3;
    const int lr   = lane >> 2;

    float acc[2][4][4];
    #pragma unroll
    for (int i = 0; i < 2; i++)
        #pragma unroll
        for (int j = 0; j < 4; j++)
            #pragma unroll
            for (int r = 0; r < 4; r++) acc[i][j][r] = 0.f;

    float4 pa[A4T], pb[B4T];
    #pragma unroll
    for (int i = 0; i < A4T; i++) {
        int idx = tid + i * THREADS;
        int row = idx >> 3, kq = (idx & 7) * 4;
        pa[i] = *(const float4*)&A[(size_t)(m0 + row) * K + kq];
    }
    #pragma unroll
    for (int i = 0; i < B4T; i++) {
        int idx = tid + i * THREADS;
        int row = idx >> 3, kq = (idx & 7) * 4;
        pb[i] = *(const float4*)&B[(size_t)(n0 + row) * K + kq];
    }

    for (int k0 = 0; k0 < K; k0 += BK) {
        #pragma unroll
        for (int i = 0; i < A4T; i++) {
            int idx = tid + i * THREADS;
            int row = idx >> 3, kq = (idx & 7) * 4;
            uint32_t h01, l01, h23, l23;
            split2(pa[i].x, pa[i].y, h01, l01);
            split2(pa[i].z, pa[i].w, h23, l23);
            int p0 = kq >> 1;
            store_pair(As, row, p0,     h01, l01);
            store_pair(As, row, p0 + 1, h23, l23);
        }
        #pragma unroll
        for (int i = 0; i < B4T; i++) {
            int idx = tid + i * THREADS;
            int row = idx >> 3, kq = (idx & 7) * 4;
            uint32_t h01, l01, h23, l23;
            split2(pb[i].x, pb[i].y, h01, l01);
            split2(pb[i].z, pb[i].w, h23, l23);
            int p0 = kq >> 1;
            store_pair(Bs, row, p0,     h01, l01);
            store_pair(Bs, row, p0 + 1, h23, l23);
        }
        __syncthreads();

        if (k0 + BK < K) {
            #pragma unroll
            for (int i = 0; i < A4T; i++) {
                int idx = tid + i * THREADS;
                int row = idx >> 3, kq = (idx & 7) * 4;
                pa[i] = *(const float4*)&A[(size_t)(m0 + row) * K + k0 + BK + kq];
            }
            #pragma unroll
            for (int i = 0; i < B4T; i++) {
                int idx = tid + i * THREADS;
                int row = idx >> 3, kq = (idx & 7) * 4;
                pb[i] = *(const float4*)&B[(size_t)(n0 + row) * K + k0 + BK + kq];
            }
        }

        const int sw = (lr & 1) << 2;
        #pragma unroll
        for (int ks = 0; ks < 2; ks++) {
            const int co = (((ks << 2) + qz) ^ sw) * 4;   // u32 offset of chunk
            uint32_t ah[2][4], al[2][4], bh[4][2], bl[4][2];
            #pragma unroll
            for (int i = 0; i < 2; i++) {
                int r0 = wm * 32 + i * 16 + lr;
                uint4 va = *(uint4*)&As[r0 * 32 + co];
                uint4 vb = *(uint4*)&As[(r0 + 8) * 32 + co];
                ah[i][0] = va.x; ah[i][2] = va.y; al[i][0] = va.z; al[i][2] = va.w;
                ah[i][1] = vb.x; ah[i][3] = vb.y; al[i][1] = vb.z; al[i][3] = vb.w;
            }
            #pragma unroll
            for (int j = 0; j < 4; j++) {
                int nr = wn * 32 + j * 8 + lr;
                uint4 v = *(uint4*)&Bs[nr * 32 + co];
                bh[j][0] = v.x; bh[j][1] = v.y; bl[j][0] = v.z; bl[j][1] = v.w;
            }
            #pragma unroll
            for (int i = 0; i < 2; i++)
                #pragma unroll
                for (int j = 0; j < 4; j++) {
                    mma_bf16(acc[i][j], ah[i], bh[j]);
                    mma_bf16(acc[i][j], al[i], bh[j]);
                    mma_bf16(acc[i][j], ah[i], bl[j]);
                }
        }
        __syncthreads();
    }

    #pragma unroll
    for (int i = 0; i < 2; i++) {
        #pragma unroll
        for (int j = 0; j < 4; j++) {
            int row = m0 + wm * 32 + i * 16 + lr;
            int col = n0 + wn * 32 + j * 8 + qz * 2;
            *(float2*)&C[(size_t)row * N + col]       = make_float2(acc[i][j][0], acc[i][j][1]);
            *(float2*)&C[(size_t)(row + 8) * N + col] = make_float2(acc[i][j][2], acc[i][j][3]);
        }
    }
}

// ---------------- MMA flash attention (RoPE fused, causal) ----------------
#define LDP 68
#define LDV 36
#define SCL2E 0.18033688f   // 0.125 * log2(e)

__global__ void __launch_bounds__(256, 2)
attn_mma(const float* __restrict__ Qg, const float* __restrict__ Kg,
         const float* __restrict__ Vg, const float* __restrict__ cosd,
         const float* __restrict__ sind, float* __restrict__ Yg)
{
    extern __shared__ uint32_t sm[];
    uint32_t* Qs  = sm;                  // [128][LDP] tf32
    uint32_t* Ks  = Qs  + 128 * LDP;     // [64][LDP]  tf32
    uint32_t* Vhi = Ks  + 64 * LDP;      // [64 d][LDV kp] packed bf16x2
    uint32_t* Vlo = Vhi + 64 * LDV;

    const int tid  = threadIdx.x;
    const int lane = tid & 31;
    const int warp = tid >> 5;
    const int qb   = (gridDim.x - 1) - blockIdx.x;
    const int h    = blockIdx.y;
    const int kvh  = h >> 3;
    const int wrow = warp * 16;
    const int r0   = wrow + (lane >> 2);
    const int qz   = lane & 3;

    for (int i = tid; i < 128 * 32; i += 256) {
        int row = i >> 5, j = i & 31;
        int n = qb * 128 + row;
        const float* qr = Qg + (size_t)n * DIM + h * HD;
        float x0 = qr[j], x1 = qr[j + 32];
        float c0 = cosd[n * HD + j],      s0 = sind[n * HD + j];
        float c1 = cosd[n * HD + 32 + j], s1 = sind[n * HD + 32 + j];
        Qs[row * LDP + j]      = f2tf((x0 * c0 - x1 * s0) * SCL2E);
        Qs[row * LDP + 32 + j] = f2tf((x1 * c1 + x0 * s1) * SCL2E);
    }

    float yacc[8][4];
    #pragma unroll
    for (int nf = 0; nf < 8; nf++)
        #pragma unroll
        for (int r = 0; r < 4; r++) yacc[nf][r] = 0.f;
    float m0 = -1e30f, m1 = -1e30f, l0 = 0.f, l1 = 0.f;

    const int arow0 = qb * 128 + r0;
    const int arow1 = arow0 + 8;
    const int ntiles = 2 * qb + 2;

    for (int t = 0; t < ntiles; t++) {
        const int s0k = t * 64;
        for (int i = tid; i < 64 * 32; i += 256) {
            int row = i >> 5, j = i & 31;
            int n = s0k + row;
            const float* kr = Kg + (size_t)n * KVDIM + kvh * HD;
            float x0 = kr[j], x1 = kr[j + 32];
            float c0 = cosd[n * HD + j],      s0 = sind[n * HD + j];
            float c1 = cosd[n * HD + 32 + j], s1 = sind[n * HD + 32 + j];
            Ks[row * LDP + j]      = f2tf(x0 * c0 - x1 * s0);
            Ks[row * LDP + 32 + j] = f2tf(x1 * c1 + x0 * s1);
        }
        for (int i = tid; i < 64 * 32; i += 256) {
            int d = i & 63, kp = i >> 6;
            float v0 = Vg[(size_t)(s0k + 2*kp)     * KVDIM + kvh * HD + d];
            float v1 = Vg[(size_t)(s0k + 2*kp + 1) * KVDIM + kvh * HD + d];
            uint32_t hi, lo;
            split2(v0, v1, hi, lo);
            Vhi[d * LDV + kp] = hi;
            Vlo[d * LDV + kp] = lo;
        }
        __syncthreads();

        float s[8][4];
        #pragma unroll
        for (int nf = 0; nf < 8; nf++)
            #pragma unroll
            for (int r = 0; r < 4; r++) s[nf][r] = 0.f;

        #pragma unroll
        for (int ki = 0; ki < 8; ki++) {
            const int c = ki * 8 + qz;
            uint32_t a[4];
            a[0] = Qs[r0 * LDP + c];
            a[1] = Qs[(r0 + 8) * LDP + c];
            a[2] = Qs[r0 * LDP + c + 4];
            a[3] = Qs[(r0 + 8) * LDP + c + 4];
            #pragma unroll
            for (int nf = 0; nf < 8; nf++) {
                const int krow = nf * 8 + (lane >> 2);
                uint32_t b[2];
                b[0] = Ks[krow * LDP + c];
                b[1] = Ks[krow * LDP + c + 4];
                mma_tf32(s[nf], a, b);
            }
        }

        if (s0k + 63 > qb * 128 + wrow) {
            #pragma unroll
            for (int nf = 0; nf < 8; nf++) {
                int key = s0k + nf * 8 + 2 * qz;
                if (key     > arow0) s[nf][0] = -1e30f;
                if (key + 1 > arow0) s[nf][1] = -1e30f;
                if (key     > arow1) s[nf][2] = -1e30f;
                if (key + 1 > arow1) s[nf][3] = -1e30f;
            }
        }

        float t0 = -1e30f, t1 = -1e30f;
        #pragma unroll
        for (int nf = 0; nf < 8; nf++) {
            t0 = fmaxf(t0, fmaxf(s[nf][0], s[nf][1]));
            t1 = fmaxf(t1, fmaxf(s[nf][2], s[nf][3]));
        }
        t0 = fmaxf(t0, __shfl_xor_sync(0xffffffff, t0, 1));
        t0 = fmaxf(t0, __shfl_xor_sync(0xffffffff, t0, 2));
        t1 = fmaxf(t1, __shfl_xor_sync(0xffffffff, t1, 1));
        t1 = fmaxf(t1, __shfl_xor_sync(0xffffffff, t1, 2));
        float nm0 = fmaxf(m0, t0), nm1 = fmaxf(m1, t1);
        float cor0 = ex2(m0 - nm0), cor1 = ex2(m1 - nm1);
        m0 = nm0; m1 = nm1;

        float ls0 = 0.f, ls1 = 0.f;
        #pragma unroll
        for (int nf = 0; nf < 8; nf++) {
            s[nf][0] = ex2(s[nf][0] - m0);
            s[nf][1] = ex2(s[nf][1] - m0);
            s[nf][2] = ex2(s[nf][2] - m1);
            s[nf][3] = ex2(s[nf][3] - m1);
            ls0 += s[nf][0] + s[nf][1];
            ls1 += s[nf][2] + s[nf][3];
        }
        ls0 += __shfl_xor_sync(0xffffffff, ls0, 1);
        ls0 += __shfl_xor_sync(0xffffffff, ls0, 2);
        ls1 += __shfl_xor_sync(0xffffffff, ls1, 1);
        ls1 += __shfl_xor_sync(0xffffffff, ls1, 2);
        l0 = l0 * cor0 + ls0;
        l1 = l1 * cor1 + ls1;
        #pragma unroll
        for (int nf = 0; nf < 8; nf++) {
            yacc[nf][0] *= cor0; yacc[nf][1] *= cor0;
            yacc[nf][2] *= cor1; yacc[nf][3] *= cor1;
        }

        #pragma unroll
        for (int ko = 0; ko < 4; ko++) {
            uint32_t ah[4], al[4];
            split2(s[2*ko][0],     s[2*ko][1],     ah[0], al[0]);
            split2(s[2*ko][2],     s[2*ko][3],     ah[1], al[1]);
            split2(s[2*ko + 1][0], s[2*ko + 1][1], ah[2], al[2]);
            split2(s[2*ko + 1][2], s[2*ko + 1][3], ah[3], al[3]);
            #pragma unroll
            for (int nf = 0; nf < 8; nf++) {
                const int d = nf * 8 + (lane >> 2);
                uint32_t bh[2], bl[2];
                bh[0] = Vhi[d * LDV + ko * 8 + qz];
                bh[1] = Vhi[d * LDV + ko * 8 + qz + 4];
                bl[0] = Vlo[d * LDV + ko * 8 + qz];
                bl[1] = Vlo[d * LDV + ko * 8 + qz + 4];
                mma_bf16(yacc[nf], ah, bh);
                mma_bf16(yacc[nf], al, bh);
                mma_bf16(yacc[nf], ah, bl);
            }
        }
        __syncthreads();
    }

    float i0 = 1.f / l0, i1 = 1.f / l1;
    #pragma unroll
    for (int nf = 0; nf < 8; nf++) {
        int col = h * HD + nf * 8 + 2 * qz;
        *(float2*)&Yg[(size_t)arow0 * DIM + col] =
            make_float2(yacc[nf][0] * i0, yacc[nf][1] * i0);
        *(float2*)&Yg[(size_t)arow1 * DIM + col] =
            make_float2(yacc[nf][2] * i1, yacc[nf][3] * i1);
    }
}

// ---------------- launch ----------------
extern "C" void kernel_launch(void* const* d_in, const int* in_sizes, int n_in,
                              void* d_out, int out_size)
{
    const float* x   = (const float*)d_in[0];
    const float* Wq  = (const float*)d_in[1];
    const float* Wk  = (const float*)d_in[2];
    const float* Wv  = (const float*)d_in[3];
    const float* Wo  = (const float*)d_in[4];
    const float* cosd= (const float*)d_in[5];
    const float* sind= (const float*)d_in[6];
    float* out = (float*)d_out;

    float *qp, *kp, *vp, *yp;
    cudaGetSymbolAddress((void**)&qp, g_q);
    cudaGetSymbolAddress((void**)&kp, g_k);
    cudaGetSymbolAddress((void**)&vp, g_v);
    cudaGetSymbolAddress((void**)&yp, g_y);

    constexpr int SMEM_G = (128 + 64) * 32 * 4;                          // 24576 B
    constexpr int SMEM_ATTN = (128 * LDP + 64 * LDP + 2 * 64 * LDV) * 4; // 70656 B
    cudaFuncSetAttribute(attn_mma,
                         cudaFuncAttributeMaxDynamicSharedMemorySize, SMEM_ATTN);

    // 1: fused K+V projections
    gemm_bf16<<<dim3(KVDIM/64, NSEQ/128, 2), 256, SMEM_G>>>(x, Wk, kp, Wv, vp, NSEQ, KVDIM, DIM);
    // 2: Q projection
    gemm_bf16<<<dim3(DIM/64, NSEQ/128, 1), 256, SMEM_G>>>(x, Wq, qp, Wq, qp, NSEQ, DIM, DIM);
    // 3: fused rope + flash attention
    attn_mma<<<dim3(16, HEADS), 256, SMEM_ATTN>>>(qp, kp, vp, cosd, sind, yp);
    // 4: output projection (profiled slot #4)
    gemm_bf16<<<dim3(DIM/64, NSEQ/128, 1), 256, SMEM_G>>>(yp, Wo, out, Wo, out, NSEQ, DIM, DIM);
}

// round 9
// speedup vs baseline: 1.1809x; 1.1809x over previous
#include <cuda_runtime.h>
#include <cuda_bf16.h>
#include <math.h>
#include <stdint.h>

// Problem constants
#define NSEQ 2048
#define DIM  2048
#define HEADS 32
#define KVHEADS 4
#define HD 64
#define KVDIM (KVHEADS*HD)   // 256
#define REP (HEADS/KVHEADS)  // 8

// ---------------- scratch ----------------
__device__ float g_q[NSEQ * DIM];
__device__ float g_k[NSEQ * KVDIM];
__device__ float g_v[NSEQ * KVDIM];
__device__ float g_y[NSEQ * DIM];

// ---------------- helpers ----------------
__device__ __forceinline__ uint32_t f2tf(float x) {
    uint32_t r;
    asm("cvt.rna.tf32.f32 %0, %1;" : "=r"(r) : "f"(x));
    return r;
}

__device__ __forceinline__ float ex2(float x) {
    float r;
    asm("ex2.approx.f32 %0, %1;" : "=f"(r) : "f"(x));
    return r;
}

__device__ __forceinline__ uint32_t pkbf(float x0, float x1) {
    __nv_bfloat162 h = __floats2bfloat162_rn(x0, x1);
    return *reinterpret_cast<uint32_t*>(&h);
}

__device__ __forceinline__ void split2(float x0, float x1, uint32_t& hi, uint32_t& lo) {
    float h0 = __bfloat162float(__float2bfloat16(x0));
    float h1 = __bfloat162float(__float2bfloat16(x1));
    hi = pkbf(h0, h1);
    lo = pkbf(x0 - h0, x1 - h1);
}

__device__ __forceinline__ void mma_tf32(float* d, const uint32_t* a, const uint32_t* b) {
    asm volatile(
        "mma.sync.aligned.m16n8k8.row.col.f32.tf32.tf32.f32 "
        "{%0,%1,%2,%3}, {%4,%5,%6,%7}, {%8,%9}, {%0,%1,%2,%3};"
        : "+f"(d[0]), "+f"(d[1]), "+f"(d[2]), "+f"(d[3])
        : "r"(a[0]), "r"(a[1]), "r"(a[2]), "r"(a[3]), "r"(b[0]), "r"(b[1]));
}

__device__ __forceinline__ void mma_bf16(float* d, const uint32_t* a, const uint32_t* b) {
    asm volatile(
        "mma.sync.aligned.m16n8k16.row.col.f32.bf16.bf16.f32 "
        "{%0,%1,%2,%3}, {%4,%5,%6,%7}, {%8,%9}, {%0,%1,%2,%3};"
        : "+f"(d[0]), "+f"(d[1]), "+f"(d[2]), "+f"(d[3])
        : "r"(a[0]), "r"(a[1]), "r"(a[2]), "r"(a[3]), "r"(b[0]), "r"(b[1]));
}

// ---------------- 3xBF16 NT GEMM core (double-buffered) ----------------
// C[m][n] = sum_k A[m][k]*B[n][k]. CTA tile 128x64, BK=32, 256 threads,
// 8 warps of 32x32. Two smem stages; one __syncthreads per k-tile:
//   LDG(s+1) -> MMA(buf s) -> STS(s+1 -> other buf) -> sync
#define GLDSW 20
#define GSA (128 * GLDSW)
#define GSB (64 * GLDSW)
#define GSTAGE (2 * GSA + 2 * GSB)   // 7680 u32 = 30720 B for both stages? no: per stage
// NOTE: per-stage block = Ah(GSA)+Al(GSA)+Bh(GSB)+Bl(GSB) = 7680 u32 (30720B total for 2)

__device__ __forceinline__ void gemm_ldg(const float* __restrict__ A,
                                         const float* __restrict__ B,
                                         int m0, int n0, int K, int k0, int tid,
                                         float4* pa, float4* pb)
{
    #pragma unroll
    for (int i = 0; i < 4; i++) {
        int idx = tid + i * 256;
        int row = idx >> 3, kq = (idx & 7) * 4;
        pa[i] = *(const float4*)&A[(size_t)(m0 + row) * K + k0 + kq];
    }
    #pragma unroll
    for (int i = 0; i < 2; i++) {
        int idx = tid + i * 256;
        int row = idx >> 3, kq = (idx & 7) * 4;
        pb[i] = *(const float4*)&B[(size_t)(n0 + row) * K + k0 + kq];
    }
}

__device__ __forceinline__ void gemm_sts(uint32_t* st, const float4* pa,
                                         const float4* pb, int tid)
{
    uint32_t* Ah = st;
    uint32_t* Al = st + GSA;
    uint32_t* Bh = st + 2 * GSA;
    uint32_t* Bl = st + 2 * GSA + GSB;
    #pragma unroll
    for (int i = 0; i < 4; i++) {
        int idx = tid + i * 256;
        int row = idx >> 3, kq = (idx & 7) * 4;
        uint32_t h01, l01, h23, l23;
        split2(pa[i].x, pa[i].y, h01, l01);
        split2(pa[i].z, pa[i].w, h23, l23);
        Ah[row * GLDSW + kq/2]     = h01;
        Ah[row * GLDSW + kq/2 + 1] = h23;
        Al[row * GLDSW + kq/2]     = l01;
        Al[row * GLDSW + kq/2 + 1] = l23;
    }
    #pragma unroll
    for (int i = 0; i < 2; i++) {
        int idx = tid + i * 256;
        int row = idx >> 3, kq = (idx & 7) * 4;
        uint32_t h01, l01, h23, l23;
        split2(pb[i].x, pb[i].y, h01, l01);
        split2(pb[i].z, pb[i].w, h23, l23);
        Bh[row * GLDSW + kq/2]     = h01;
        Bh[row * GLDSW + kq/2 + 1] = h23;
        Bl[row * GLDSW + kq/2]     = l01;
        Bl[row * GLDSW + kq/2 + 1] = l23;
    }
}

__device__ __forceinline__ void gemm_core(const float* __restrict__ A,
                                          const float* __restrict__ B,
                                          float* __restrict__ C,
                                          int m0, int n0, int N, int K,
                                          uint32_t* sm)
{
    constexpr int BK = 32;
    const int tid  = threadIdx.x;
    const int lane = tid & 31;
    const int warp = tid >> 5;
    const int wm   = warp >> 1;
    const int wn   = warp & 1;
    const int qz   = lane & 3;
    const int lr   = lane >> 2;

    float acc[2][4][4];
    #pragma unroll
    for (int i = 0; i < 2; i++)
        #pragma unroll
        for (int j = 0; j < 4; j++)
            #pragma unroll
            for (int r = 0; r < 4; r++) acc[i][j][r] = 0.f;

    float4 pa[4], pb[2];
    // prologue: LDG(0) + STS(0)
    gemm_ldg(A, B, m0, n0, K, 0, tid, pa, pb);
    gemm_sts(sm, pa, pb, tid);
    __syncthreads();

    const int S = K / BK;
    for (int s = 0; s < S; s++) {
        uint32_t* st = sm + (s & 1) * (2 * GSA + 2 * GSB);
        uint32_t* Ah = st;
        uint32_t* Al = st + GSA;
        uint32_t* Bh = st + 2 * GSA;
        uint32_t* Bl = st + 2 * GSA + GSB;

        // prefetch next tile to registers (overlaps MMA below)
        if (s + 1 < S)
            gemm_ldg(A, B, m0, n0, K, (s + 1) * BK, tid, pa, pb);

        #pragma unroll
        for (int ks = 0; ks < 2; ks++) {
            const int c0 = ks * 8 + qz;
            uint32_t ah[2][4], al[2][4], bh[4][2], bl[4][2];
            #pragma unroll
            for (int i = 0; i < 2; i++) {
                int r0 = wm * 32 + i * 16 + lr;
                ah[i][0] = Ah[r0 * GLDSW + c0];
                ah[i][1] = Ah[(r0 + 8) * GLDSW + c0];
                ah[i][2] = Ah[r0 * GLDSW + c0 + 4];
                ah[i][3] = Ah[(r0 + 8) * GLDSW + c0 + 4];
                al[i][0] = Al[r0 * GLDSW + c0];
                al[i][1] = Al[(r0 + 8) * GLDSW + c0];
                al[i][2] = Al[r0 * GLDSW + c0 + 4];
                al[i][3] = Al[(r0 + 8) * GLDSW + c0 + 4];
            }
            #pragma unroll
            for (int j = 0; j < 4; j++) {
                int nr = wn * 32 + j * 8 + lr;
                bh[j][0] = Bh[nr * GLDSW + c0];
                bh[j][1] = Bh[nr * GLDSW + c0 + 4];
                bl[j][0] = Bl[nr * GLDSW + c0];
                bl[j][1] = Bl[nr * GLDSW + c0 + 4];
            }
            #pragma unroll
            for (int i = 0; i < 2; i++)
                #pragma unroll
                for (int j = 0; j < 4; j++) {
                    mma_bf16(acc[i][j], ah[i], bh[j]);
                    mma_bf16(acc[i][j], al[i], bh[j]);
                    mma_bf16(acc[i][j], ah[i], bl[j]);
                }
        }

        // store next tile into the other buffer (overlaps other warps' MMA)
        if (s + 1 < S)
            gemm_sts(sm + ((s + 1) & 1) * (2 * GSA + 2 * GSB), pa, pb, tid);
        __syncthreads();
    }

    #pragma unroll
    for (int i = 0; i < 2; i++) {
        #pragma unroll
        for (int j = 0; j < 4; j++) {
            int row = m0 + wm * 32 + i * 16 + lr;
            int col = n0 + wn * 32 + j * 8 + qz * 2;
            *(float2*)&C[(size_t)row * N + col]       = make_float2(acc[i][j][0], acc[i][j][1]);
            *(float2*)&C[(size_t)(row + 8) * N + col] = make_float2(acc[i][j][2], acc[i][j][3]);
        }
    }
}

// ---- fused Q+K+V projection: blockIdx.x routes to Wq (0..31), Wk (32..35), Wv (36..39)
__global__ void __launch_bounds__(256, 2)
proj_qkv(const float* __restrict__ x,
         const float* __restrict__ Wq, float* __restrict__ qp,
         const float* __restrict__ Wk, float* __restrict__ kp,
         const float* __restrict__ Wv, float* __restrict__ vp)
{
    extern __shared__ uint32_t sm[];
    const int bx = blockIdx.x;
    const int m0 = blockIdx.y * 128;
    if (bx < 32) {
        gemm_core(x, Wq, qp, m0, bx * 64, DIM, DIM, sm);
    } else if (bx < 36) {
        gemm_core(x, Wk, kp, m0, (bx - 32) * 64, KVDIM, DIM, sm);
    } else {
        gemm_core(x, Wv, vp, m0, (bx - 36) * 64, KVDIM, DIM, sm);
    }
}

__global__ void __launch_bounds__(256, 2)
proj_o(const float* __restrict__ yp, const float* __restrict__ Wo,
       float* __restrict__ out)
{
    extern __shared__ uint32_t sm[];
    gemm_core(yp, Wo, out, blockIdx.y * 128, blockIdx.x * 64, DIM, DIM, sm);
}

// ---------------- MMA flash attention (RoPE fused, causal) — R6 version ----------------
#define LDP 68
#define LDV 36
#define SCL2E 0.18033688f   // 0.125 * log2(e)

__global__ void __launch_bounds__(256, 2)
attn_mma(const float* __restrict__ Qg, const float* __restrict__ Kg,
         const float* __restrict__ Vg, const float* __restrict__ cosd,
         const float* __restrict__ sind, float* __restrict__ Yg)
{
    extern __shared__ uint32_t sm[];
    uint32_t* Qs  = sm;                  // [128][LDP] tf32
    uint32_t* Ks  = Qs  + 128 * LDP;     // [64][LDP]  tf32
    uint32_t* Vhi = Ks  + 64 * LDP;      // [64 d][LDV kp] packed bf16x2
    uint32_t* Vlo = Vhi + 64 * LDV;

    const int tid  = threadIdx.x;
    const int lane = tid & 31;
    const int warp = tid >> 5;
    const int qb   = (gridDim.x - 1) - blockIdx.x;
    const int h    = blockIdx.y;
    const int kvh  = h >> 3;
    const int wrow = warp * 16;
    const int r0   = wrow + (lane >> 2);
    const int qz   = lane & 3;

    for (int i = tid; i < 128 * 32; i += 256) {
        int row = i >> 5, j = i & 31;
        int n = qb * 128 + row;
        const float* qr = Qg + (size_t)n * DIM + h * HD;
        float x0 = qr[j], x1 = qr[j + 32];
        float c0 = cosd[n * HD + j],      s0 = sind[n * HD + j];
        float c1 = cosd[n * HD + 32 + j], s1 = sind[n * HD + 32 + j];
        Qs[row * LDP + j]      = f2tf((x0 * c0 - x1 * s0) * SCL2E);
        Qs[row * LDP + 32 + j] = f2tf((x1 * c1 + x0 * s1) * SCL2E);
    }

    float yacc[8][4];
    #pragma unroll
    for (int nf = 0; nf < 8; nf++)
        #pragma unroll
        for (int r = 0; r < 4; r++) yacc[nf][r] = 0.f;
    float m0 = -1e30f, m1 = -1e30f, l0 = 0.f, l1 = 0.f;

    const int arow0 = qb * 128 + r0;
    const int arow1 = arow0 + 8;
    const int ntiles = 2 * qb + 2;

    for (int t = 0; t < ntiles; t++) {
        const int s0k = t * 64;
        for (int i = tid; i < 64 * 32; i += 256) {
            int row = i >> 5, j = i & 31;
            int n = s0k + row;
            const float* kr = Kg + (size_t)n * KVDIM + kvh * HD;
            float x0 = kr[j], x1 = kr[j + 32];
            float c0 = cosd[n * HD + j],      s0 = sind[n * HD + j];
            float c1 = cosd[n * HD + 32 + j], s1 = sind[n * HD + 32 + j];
            Ks[row * LDP + j]      = f2tf(x0 * c0 - x1 * s0);
            Ks[row * LDP + 32 + j] = f2tf(x1 * c1 + x0 * s1);
        }
        for (int i = tid; i < 64 * 32; i += 256) {
            int d = i & 63, kp = i >> 6;
            float v0 = Vg[(size_t)(s0k + 2*kp)     * KVDIM + kvh * HD + d];
            float v1 = Vg[(size_t)(s0k + 2*kp + 1) * KVDIM + kvh * HD + d];
            uint32_t hi, lo;
            split2(v0, v1, hi, lo);
            Vhi[d * LDV + kp] = hi;
            Vlo[d * LDV + kp] = lo;
        }
        __syncthreads();

        float s[8][4];
        #pragma unroll
        for (int nf = 0; nf < 8; nf++)
            #pragma unroll
            for (int r = 0; r < 4; r++) s[nf][r] = 0.f;

        #pragma unroll
        for (int ki = 0; ki < 8; ki++) {
            const int c = ki * 8 + qz;
            uint32_t a[4];
            a[0] = Qs[r0 * LDP + c];
            a[1] = Qs[(r0 + 8) * LDP + c];
            a[2] = Qs[r0 * LDP + c + 4];
            a[3] = Qs[(r0 + 8) * LDP + c + 4];
            #pragma unroll
            for (int nf = 0; nf < 8; nf++) {
                const int krow = nf * 8 + (lane >> 2);
                uint32_t b[2];
                b[0] = Ks[krow * LDP + c];
                b[1] = Ks[krow * LDP + c + 4];
                mma_tf32(s[nf], a, b);
            }
        }

        if (s0k + 63 > qb * 128 + wrow) {
            #pragma unroll
            for (int nf = 0; nf < 8; nf++) {
                int key = s0k + nf * 8 + 2 * qz;
                if (key     > arow0) s[nf][0] = -1e30f;
                if (key + 1 > arow0) s[nf][1] = -1e30f;
                if (key     > arow1) s[nf][2] = -1e30f;
                if (key + 1 > arow1) s[nf][3] = -1e30f;
            }
        }

        float t0 = -1e30f, t1 = -1e30f;
        #pragma unroll
        for (int nf = 0; nf < 8; nf++) {
            t0 = fmaxf(t0, fmaxf(s[nf][0], s[nf][1]));
            t1 = fmaxf(t1, fmaxf(s[nf][2], s[nf][3]));
        }
        t0 = fmaxf(t0, __shfl_xor_sync(0xffffffff, t0, 1));
        t0 = fmaxf(t0, __shfl_xor_sync(0xffffffff, t0, 2));
        t1 = fmaxf(t1, __shfl_xor_sync(0xffffffff, t1, 1));
        t1 = fmaxf(t1, __shfl_xor_sync(0xffffffff, t1, 2));
        float nm0 = fmaxf(m0, t0), nm1 = fmaxf(m1, t1);
        float cor0 = ex2(m0 - nm0), cor1 = ex2(m1 - nm1);
        m0 = nm0; m1 = nm1;

        float ls0 = 0.f, ls1 = 0.f;
        #pragma unroll
        for (int nf = 0; nf < 8; nf++) {
            s[nf][0] = ex2(s[nf][0] - m0);
            s[nf][1] = ex2(s[nf][1] - m0);
            s[nf][2] = ex2(s[nf][2] - m1);
            s[nf][3] = ex2(s[nf][3] - m1);
            ls0 += s[nf][0] + s[nf][1];
            ls1 += s[nf][2] + s[nf][3];
        }
        ls0 += __shfl_xor_sync(0xffffffff, ls0, 1);
        ls0 += __shfl_xor_sync(0xffffffff, ls0, 2);
        ls1 += __shfl_xor_sync(0xffffffff, ls1, 1);
        ls1 += __shfl_xor_sync(0xffffffff, ls1, 2);
        l0 = l0 * cor0 + ls0;
        l1 = l1 * cor1 + ls1;
        #pragma unroll
        for (int nf = 0; nf < 8; nf++) {
            yacc[nf][0] *= cor0; yacc[nf][1] *= cor0;
            yacc[nf][2] *= cor1; yacc[nf][3] *= cor1;
        }

        #pragma unroll
        for (int ko = 0; ko < 4; ko++) {
            uint32_t ah[4], al[4];
            split2(s[2*ko][0],     s[2*ko][1],     ah[0], al[0]);
            split2(s[2*ko][2],     s[2*ko][3],     ah[1], al[1]);
            split2(s[2*ko + 1][0], s[2*ko + 1][1], ah[2], al[2]);
            split2(s[2*ko + 1][2], s[2*ko + 1][3], ah[3], al[3]);
            #pragma unroll
            for (int nf = 0; nf < 8; nf++) {
                const int d = nf * 8 + (lane >> 2);
                uint32_t bh[2], bl[2];
                bh[0] = Vhi[d * LDV + ko * 8 + qz];
                bh[1] = Vhi[d * LDV + ko * 8 + qz + 4];
                bl[0] = Vlo[d * LDV + ko * 8 + qz];
                bl[1] = Vlo[d * LDV + ko * 8 + qz + 4];
                mma_bf16(yacc[nf], ah, bh);
                mma_bf16(yacc[nf], al, bh);
                mma_bf16(yacc[nf], ah, bl);
            }
        }
        __syncthreads();
    }

    float i0 = 1.f / l0, i1 = 1.f / l1;
    #pragma unroll
    for (int nf = 0; nf < 8; nf++) {
        int col = h * HD + nf * 8 + 2 * qz;
        *(float2*)&Yg[(size_t)arow0 * DIM + col] =
            make_float2(yacc[nf][0] * i0, yacc[nf][1] * i0);
        *(float2*)&Yg[(size_t)arow1 * DIM + col] =
            make_float2(yacc[nf][2] * i1, yacc[nf][3] * i1);
    }
}

// ---------------- launch ----------------
extern "C" void kernel_launch(void* const* d_in, const int* in_sizes, int n_in,
                              void* d_out, int out_size)
{
    const float* x   = (const float*)d_in[0];
    const float* Wq  = (const float*)d_in[1];
    const float* Wk  = (const float*)d_in[2];
    const float* Wv  = (const float*)d_in[3];
    const float* Wo  = (const float*)d_in[4];
    const float* cosd= (const float*)d_in[5];
    const float* sind= (const float*)d_in[6];
    float* out = (float*)d_out;

    float *qp, *kp, *vp, *yp;
    cudaGetSymbolAddress((void**)&qp, g_q);
    cudaGetSymbolAddress((void**)&kp, g_k);
    cudaGetSymbolAddress((void**)&vp, g_v);
    cudaGetSymbolAddress((void**)&yp, g_y);

    constexpr int SMEM_G = 2 * (2 * GSA + 2 * GSB) * 4;                  // 61440 B? no: 2 stages *7680 u32*4 = 61440
    constexpr int SMEM_ATTN = (128 * LDP + 64 * LDP + 2 * 64 * LDV) * 4; // 70656 B
    cudaFuncSetAttribute(proj_qkv,
                         cudaFuncAttributeMaxDynamicSharedMemorySize, SMEM_G);
    cudaFuncSetAttribute(proj_o,
                         cudaFuncAttributeMaxDynamicSharedMemorySize, SMEM_G);
    cudaFuncSetAttribute(attn_mma,
                         cudaFuncAttributeMaxDynamicSharedMemorySize, SMEM_ATTN);

    // 1: fused Q+K+V projections (x<32: Q, 32-35: K, 36-39: V)
    proj_qkv<<<dim3(40, 16), 256, SMEM_G>>>(x, Wq, qp, Wk, kp, Wv, vp);
    // 2: fused rope + flash attention
    attn_mma<<<dim3(16, HEADS), 256, SMEM_ATTN>>>(qp, kp, vp, cosd, sind, yp);
    // 3: output projection
    proj_o<<<dim3(32, 16), 256, SMEM_G>>>(yp, Wo, out);
}

// round 10
// speedup vs baseline: 1.4844x; 1.2570x over previous
#include <cuda_runtime.h>
#include <cuda_bf16.h>
#include <cuda_fp16.h>
#include <math.h>
#include <stdint.h>

// Problem constants
#define NSEQ 2048
#define DIM  2048
#define HEADS 32
#define KVHEADS 4
#define HD 64
#define KVDIM (KVHEADS*HD)   // 256
#define REP (HEADS/KVHEADS)  // 8

// ---------------- scratch ----------------
__device__ float g_q[NSEQ * DIM];
__device__ float g_k[NSEQ * KVDIM];
__device__ float g_v[NSEQ * KVDIM];
__device__ float g_y[NSEQ * DIM];

// ---------------- helpers ----------------
__device__ __forceinline__ uint32_t f2tf(float x) {
    uint32_t r;
    asm("cvt.rna.tf32.f32 %0, %1;" : "=r"(r) : "f"(x));
    return r;
}

__device__ __forceinline__ float ex2(float x) {
    float r;
    asm("ex2.approx.f32 %0, %1;" : "=f"(r) : "f"(x));
    return r;
}

__device__ __forceinline__ uint32_t pkhf(float x0, float x1) {
    __half2 h = __floats2half2_rn(x0, x1);
    return *reinterpret_cast<uint32_t*>(&h);
}

// fp16 hi/lo split (packed pairs)
__device__ __forceinline__ void split2h(float x0, float x1, uint32_t& hi, uint32_t& lo) {
    float h0 = __half2float(__float2half_rn(x0));
    float h1 = __half2float(__float2half_rn(x1));
    hi = pkhf(h0, h1);
    lo = pkhf(x0 - h0, x1 - h1);
}

__device__ __forceinline__ void mma_tf32(float* d, const uint32_t* a, const uint32_t* b) {
    asm volatile(
        "mma.sync.aligned.m16n8k8.row.col.f32.tf32.tf32.f32 "
        "{%0,%1,%2,%3}, {%4,%5,%6,%7}, {%8,%9}, {%0,%1,%2,%3};"
        : "+f"(d[0]), "+f"(d[1]), "+f"(d[2]), "+f"(d[3])
        : "r"(a[0]), "r"(a[1]), "r"(a[2]), "r"(a[3]), "r"(b[0]), "r"(b[1]));
}

__device__ __forceinline__ void mma_f16(float* d, const uint32_t* a, const uint32_t* b) {
    asm volatile(
        "mma.sync.aligned.m16n8k16.row.col.f32.f16.f16.f32 "
        "{%0,%1,%2,%3}, {%4,%5,%6,%7}, {%8,%9}, {%0,%1,%2,%3};"
        : "+f"(d[0]), "+f"(d[1]), "+f"(d[2]), "+f"(d[3])
        : "r"(a[0]), "r"(a[1]), "r"(a[2]), "r"(a[3]), "r"(b[0]), "r"(b[1]));
}

// ---------------- 2xFP16 NT GEMM core (double-buffered) ----------------
// C = A(hi) * (B(hi) + B(lo))^T : dropped term a_lo*b ~ 2^-11 relative.
// CTA tile 128x64, BK=32, 256 threads, 8 warps of 32x32.
// One __syncthreads per k-tile: LDG(s+1) -> MMA(s) -> STS(s+1) -> sync.
#define GLDSW 20
#define GSA (128 * GLDSW)            // A hi plane (u32)
#define GSB (64 * GLDSW)             // one B plane (u32)
#define GSTAGE (GSA + 2 * GSB)       // 5120 u32 per stage

__device__ __forceinline__ void gemm_ldg(const float* __restrict__ A,
                                         const float* __restrict__ B,
                                         int m0, int n0, int K, int k0, int tid,
                                         float4* pa, float4* pb)
{
    #pragma unroll
    for (int i = 0; i < 4; i++) {
        int idx = tid + i * 256;
        int row = idx >> 3, kq = (idx & 7) * 4;
        pa[i] = *(const float4*)&A[(size_t)(m0 + row) * K + k0 + kq];
    }
    #pragma unroll
    for (int i = 0; i < 2; i++) {
        int idx = tid + i * 256;
        int row = idx >> 3, kq = (idx & 7) * 4;
        pb[i] = *(const float4*)&B[(size_t)(n0 + row) * K + k0 + kq];
    }
}

__device__ __forceinline__ void gemm_sts(uint32_t* st, const float4* pa,
                                         const float4* pb, int tid)
{
    uint32_t* Ah = st;
    uint32_t* Bh = st + GSA;
    uint32_t* Bl = st + GSA + GSB;
    #pragma unroll
    for (int i = 0; i < 4; i++) {
        int idx = tid + i * 256;
        int row = idx >> 3, kq = (idx & 7) * 4;
        Ah[row * GLDSW + kq/2]     = pkhf(pa[i].x, pa[i].y);
        Ah[row * GLDSW + kq/2 + 1] = pkhf(pa[i].z, pa[i].w);
    }
    #pragma unroll
    for (int i = 0; i < 2; i++) {
        int idx = tid + i * 256;
        int row = idx >> 3, kq = (idx & 7) * 4;
        uint32_t h01, l01, h23, l23;
        split2h(pb[i].x, pb[i].y, h01, l01);
        split2h(pb[i].z, pb[i].w, h23, l23);
        Bh[row * GLDSW + kq/2]     = h01;
        Bh[row * GLDSW + kq/2 + 1] = h23;
        Bl[row * GLDSW + kq/2]     = l01;
        Bl[row * GLDSW + kq/2 + 1] = l23;
    }
}

__device__ __forceinline__ void gemm_core(const float* __restrict__ A,
                                          const float* __restrict__ B,
                                          float* __restrict__ C,
                                          int m0, int n0, int N, int K,
                                          uint32_t* sm)
{
    constexpr int BK = 32;
    const int tid  = threadIdx.x;
    const int lane = tid & 31;
    const int warp = tid >> 5;
    const int wm   = warp >> 1;
    const int wn   = warp & 1;
    const int qz   = lane & 3;
    const int lr   = lane >> 2;

    float acc[2][4][4];
    #pragma unroll
    for (int i = 0; i < 2; i++)
        #pragma unroll
        for (int j = 0; j < 4; j++)
            #pragma unroll
            for (int r = 0; r < 4; r++) acc[i][j][r] = 0.f;

    float4 pa[4], pb[2];
    gemm_ldg(A, B, m0, n0, K, 0, tid, pa, pb);
    gemm_sts(sm, pa, pb, tid);
    __syncthreads();

    const int S = K / BK;
    for (int s = 0; s < S; s++) {
        uint32_t* st = sm + (s & 1) * GSTAGE;
        uint32_t* Ah = st;
        uint32_t* Bh = st + GSA;
        uint32_t* Bl = st + GSA + GSB;

        if (s + 1 < S)
            gemm_ldg(A, B, m0, n0, K, (s + 1) * BK, tid, pa, pb);

        #pragma unroll
        for (int ks = 0; ks < 2; ks++) {
            const int c0 = ks * 8 + qz;
            uint32_t ah[2][4], bh[4][2], bl[4][2];
            #pragma unroll
            for (int i = 0; i < 2; i++) {
                int r0 = wm * 32 + i * 16 + lr;
                ah[i][0] = Ah[r0 * GLDSW + c0];
                ah[i][1] = Ah[(r0 + 8) * GLDSW + c0];
                ah[i][2] = Ah[r0 * GLDSW + c0 + 4];
                ah[i][3] = Ah[(r0 + 8) * GLDSW + c0 + 4];
            }
            #pragma unroll
            for (int j = 0; j < 4; j++) {
                int nr = wn * 32 + j * 8 + lr;
                bh[j][0] = Bh[nr * GLDSW + c0];
                bh[j][1] = Bh[nr * GLDSW + c0 + 4];
                bl[j][0] = Bl[nr * GLDSW + c0];
                bl[j][1] = Bl[nr * GLDSW + c0 + 4];
            }
            #pragma unroll
            for (int i = 0; i < 2; i++)
                #pragma unroll
                for (int j = 0; j < 4; j++) {
                    mma_f16(acc[i][j], ah[i], bh[j]);
                    mma_f16(acc[i][j], ah[i], bl[j]);
                }
        }

        if (s + 1 < S)
            gemm_sts(sm + ((s + 1) & 1) * GSTAGE, pa, pb, tid);
        __syncthreads();
    }

    #pragma unroll
    for (int i = 0; i < 2; i++) {
        #pragma unroll
        for (int j = 0; j < 4; j++) {
            int row = m0 + wm * 32 + i * 16 + lr;
            int col = n0 + wn * 32 + j * 8 + qz * 2;
            *(float2*)&C[(size_t)row * N + col]       = make_float2(acc[i][j][0], acc[i][j][1]);
            *(float2*)&C[(size_t)(row + 8) * N + col] = make_float2(acc[i][j][2], acc[i][j][3]);
        }
    }
}

// ---- fused Q+K+V projection: blockIdx.x routes to Wq (0..31), Wk (32..35), Wv (36..39)
__global__ void __launch_bounds__(256, 2)
proj_qkv(const float* __restrict__ x,
         const float* __restrict__ Wq, float* __restrict__ qp,
         const float* __restrict__ Wk, float* __restrict__ kp,
         const float* __restrict__ Wv, float* __restrict__ vp)
{
    extern __shared__ uint32_t sm[];
    const int bx = blockIdx.x;
    const int m0 = blockIdx.y * 128;
    if (bx < 32) {
        gemm_core(x, Wq, qp, m0, bx * 64, DIM, DIM, sm);
    } else if (bx < 36) {
        gemm_core(x, Wk, kp, m0, (bx - 32) * 64, KVDIM, DIM, sm);
    } else {
        gemm_core(x, Wv, vp, m0, (bx - 36) * 64, KVDIM, DIM, sm);
    }
}

__global__ void __launch_bounds__(256, 2)
proj_o(const float* __restrict__ yp, const float* __restrict__ Wo,
       float* __restrict__ out)
{
    extern __shared__ uint32_t sm[];
    gemm_core(yp, Wo, out, blockIdx.y * 128, blockIdx.x * 64, DIM, DIM, sm);
}

// ---------------- MMA flash attention (RoPE fused, causal) ----------------
// Scores: single tf32 (scale*log2e folded into Q). PV: 2xfp16, P hi-only.
#define LDP 68
#define LDV 36
#define SCL2E 0.18033688f   // 0.125 * log2(e)

__global__ void __launch_bounds__(256, 2)
attn_mma(const float* __restrict__ Qg, const float* __restrict__ Kg,
         const float* __restrict__ Vg, const float* __restrict__ cosd,
         const float* __restrict__ sind, float* __restrict__ Yg)
{
    extern __shared__ uint32_t sm[];
    uint32_t* Qs  = sm;                  // [128][LDP] tf32
    uint32_t* Ks  = Qs  + 128 * LDP;     // [64][LDP]  tf32
    uint32_t* Vhi = Ks  + 64 * LDP;      // [64 d][LDV kp] packed fp16x2
    uint32_t* Vlo = Vhi + 64 * LDV;

    const int tid  = threadIdx.x;
    const int lane = tid & 31;
    const int warp = tid >> 5;
    const int qb   = (gridDim.x - 1) - blockIdx.x;
    const int h    = blockIdx.y;
    const int kvh  = h >> 3;
    const int wrow = warp * 16;
    const int r0   = wrow + (lane >> 2);
    const int qz   = lane & 3;

    for (int i = tid; i < 128 * 32; i += 256) {
        int row = i >> 5, j = i & 31;
        int n = qb * 128 + row;
        const float* qr = Qg + (size_t)n * DIM + h * HD;
        float x0 = qr[j], x1 = qr[j + 32];
        float c0 = cosd[n * HD + j],      s0 = sind[n * HD + j];
        float c1 = cosd[n * HD + 32 + j], s1 = sind[n * HD + 32 + j];
        Qs[row * LDP + j]      = f2tf((x0 * c0 - x1 * s0) * SCL2E);
        Qs[row * LDP + 32 + j] = f2tf((x1 * c1 + x0 * s1) * SCL2E);
    }

    float yacc[8][4];
    #pragma unroll
    for (int nf = 0; nf < 8; nf++)
        #pragma unroll
        for (int r = 0; r < 4; r++) yacc[nf][r] = 0.f;
    float m0 = -1e30f, m1 = -1e30f, l0 = 0.f, l1 = 0.f;

    const int arow0 = qb * 128 + r0;
    const int arow1 = arow0 + 8;
    const int ntiles = 2 * qb + 2;

    for (int t = 0; t < ntiles; t++) {
        const int s0k = t * 64;
        for (int i = tid; i < 64 * 32; i += 256) {
            int row = i >> 5, j = i & 31;
            int n = s0k + row;
            const float* kr = Kg + (size_t)n * KVDIM + kvh * HD;
            float x0 = kr[j], x1 = kr[j + 32];
            float c0 = cosd[n * HD + j],      s0 = sind[n * HD + j];
            float c1 = cosd[n * HD + 32 + j], s1 = sind[n * HD + 32 + j];
            Ks[row * LDP + j]      = f2tf(x0 * c0 - x1 * s0);
            Ks[row * LDP + 32 + j] = f2tf(x1 * c1 + x0 * s1);
        }
        for (int i = tid; i < 64 * 32; i += 256) {
            int d = i & 63, kp = i >> 6;
            float v0 = Vg[(size_t)(s0k + 2*kp)     * KVDIM + kvh * HD + d];
            float v1 = Vg[(size_t)(s0k + 2*kp + 1) * KVDIM + kvh * HD + d];
            uint32_t hi, lo;
            split2h(v0, v1, hi, lo);
            Vhi[d * LDV + kp] = hi;
            Vlo[d * LDV + kp] = lo;
        }
        __syncthreads();

        float s[8][4];
        #pragma unroll
        for (int nf = 0; nf < 8; nf++)
            #pragma unroll
            for (int r = 0; r < 4; r++) s[nf][r] = 0.f;

        #pragma unroll
        for (int ki = 0; ki < 8; ki++) {
            const int c = ki * 8 + qz;
            uint32_t a[4];
            a[0] = Qs[r0 * LDP + c];
            a[1] = Qs[(r0 + 8) * LDP + c];
            a[2] = Qs[r0 * LDP + c + 4];
            a[3] = Qs[(r0 + 8) * LDP + c + 4];
            #pragma unroll
            for (int nf = 0; nf < 8; nf++) {
                const int krow = nf * 8 + (lane >> 2);
                uint32_t b[2];
                b[0] = Ks[krow * LDP + c];
                b[1] = Ks[krow * LDP + c + 4];
                mma_tf32(s[nf], a, b);
            }
        }

        if (s0k + 63 > qb * 128 + wrow) {
            #pragma unroll
            for (int nf = 0; nf < 8; nf++) {
                int key = s0k + nf * 8 + 2 * qz;
                if (key     > arow0) s[nf][0] = -1e30f;
                if (key + 1 > arow0) s[nf][1] = -1e30f;
                if (key     > arow1) s[nf][2] = -1e30f;
                if (key + 1 > arow1) s[nf][3] = -1e30f;
            }
        }

        float t0 = -1e30f, t1 = -1e30f;
        #pragma unroll
        for (int nf = 0; nf < 8; nf++) {
            t0 = fmaxf(t0, fmaxf(s[nf][0], s[nf][1]));
            t1 = fmaxf(t1, fmaxf(s[nf][2], s[nf][3]));
        }
        t0 = fmaxf(t0, __shfl_xor_sync(0xffffffff, t0, 1));
        t0 = fmaxf(t0, __shfl_xor_sync(0xffffffff, t0, 2));
        t1 = fmaxf(t1, __shfl_xor_sync(0xffffffff, t1, 1));
        t1 = fmaxf(t1, __shfl_xor_sync(0xffffffff, t1, 2));
        float nm0 = fmaxf(m0, t0), nm1 = fmaxf(m1, t1);
        float cor0 = ex2(m0 - nm0), cor1 = ex2(m1 - nm1);
        m0 = nm0; m1 = nm1;

        float ls0 = 0.f, ls1 = 0.f;
        #pragma unroll
        for (int nf = 0; nf < 8; nf++) {
            s[nf][0] = ex2(s[nf][0] - m0);
            s[nf][1] = ex2(s[nf][1] - m0);
            s[nf][2] = ex2(s[nf][2] - m1);
            s[nf][3] = ex2(s[nf][3] - m1);
            ls0 += s[nf][0] + s[nf][1];
            ls1 += s[nf][2] + s[nf][3];
        }
        ls0 += __shfl_xor_sync(0xffffffff, ls0, 1);
        ls0 += __shfl_xor_sync(0xffffffff, ls0, 2);
        ls1 += __shfl_xor_sync(0xffffffff, ls1, 1);
        ls1 += __shfl_xor_sync(0xffffffff, ls1, 2);
        l0 = l0 * cor0 + ls0;
        l1 = l1 * cor1 + ls1;
        #pragma unroll
        for (int nf = 0; nf < 8; nf++) {
            yacc[nf][0] *= cor0; yacc[nf][1] *= cor0;
            yacc[nf][2] *= cor1; yacc[nf][3] *= cor1;
        }

        // ---- PV: 2xfp16, P hi-only (a-frag), V = hi+lo planes ----
        #pragma unroll
        for (int ko = 0; ko < 4; ko++) {
            uint32_t ah[4];
            ah[0] = pkhf(s[2*ko][0],     s[2*ko][1]);
            ah[1] = pkhf(s[2*ko][2],     s[2*ko][3]);
            ah[2] = pkhf(s[2*ko + 1][0], s[2*ko + 1][1]);
            ah[3] = pkhf(s[2*ko + 1][2], s[2*ko + 1][3]);
            #pragma unroll
            for (int nf = 0; nf < 8; nf++) {
                const int d = nf * 8 + (lane >> 2);
                uint32_t bh[2], bl[2];
                bh[0] = Vhi[d * LDV + ko * 8 + qz];
                bh[1] = Vhi[d * LDV + ko * 8 + qz + 4];
                bl[0] = Vlo[d * LDV + ko * 8 + qz];
                bl[1] = Vlo[d * LDV + ko * 8 + qz + 4];
                mma_f16(yacc[nf], ah, bh);
                mma_f16(yacc[nf], ah, bl);
            }
        }
        __syncthreads();
    }

    float i0 = 1.f / l0, i1 = 1.f / l1;
    #pragma unroll
    for (int nf = 0; nf < 8; nf++) {
        int col = h * HD + nf * 8 + 2 * qz;
        *(float2*)&Yg[(size_t)arow0 * DIM + col] =
            make_float2(yacc[nf][0] * i0, yacc[nf][1] * i0);
        *(float2*)&Yg[(size_t)arow1 * DIM + col] =
            make_float2(yacc[nf][2] * i1, yacc[nf][3] * i1);
    }
}

// ---------------- launch ----------------
extern "C" void kernel_launch(void* const* d_in, const int* in_sizes, int n_in,
                              void* d_out, int out_size)
{
    const float* x   = (const float*)d_in[0];
    const float* Wq  = (const float*)d_in[1];
    const float* Wk  = (const float*)d_in[2];
    const float* Wv  = (const float*)d_in[3];
    const float* Wo  = (const float*)d_in[4];
    const float* cosd= (const float*)d_in[5];
    const float* sind= (const float*)d_in[6];
    float* out = (float*)d_out;

    float *qp, *kp, *vp, *yp;
    cudaGetSymbolAddress((void**)&qp, g_q);
    cudaGetSymbolAddress((void**)&kp, g_k);
    cudaGetSymbolAddress((void**)&vp, g_v);
    cudaGetSymbolAddress((void**)&yp, g_y);

    constexpr int SMEM_G = 2 * GSTAGE * 4;                               // 40960 B
    constexpr int SMEM_ATTN = (128 * LDP + 64 * LDP + 2 * 64 * LDV) * 4; // 70656 B
    cudaFuncSetAttribute(proj_qkv,
                         cudaFuncAttributeMaxDynamicSharedMemorySize, SMEM_G);
    cudaFuncSetAttribute(proj_o,
                         cudaFuncAttributeMaxDynamicSharedMemorySize, SMEM_G);
    cudaFuncSetAttribute(attn_mma,
                         cudaFuncAttributeMaxDynamicSharedMemorySize, SMEM_ATTN);

    // 1: fused Q+K+V projections (x<32: Q, 32-35: K, 36-39: V)
    proj_qkv<<<dim3(40, 16), 256, SMEM_G>>>(x, Wq, qp, Wk, kp, Wv, vp);
    // 2: fused rope + flash attention
    attn_mma<<<dim3(16, HEADS), 256, SMEM_ATTN>>>(qp, kp, vp, cosd, sind, yp);
    // 3: output projection
    proj_o<<<dim3(32, 16), 256, SMEM_G>>>(yp, Wo, out);
}